// round 15
// baseline (speedup 1.0000x reference)
#include <cuda_runtime.h>
#include <cstdint>

#define NND 32768
#define NE  491520
#define FIN 11
#define HD  64
#define NG  2048
#define NPG 16
#define NR  1024
#define NL  4
#define EINC 129
#define NINC 139
#define TE  128
#define SVT 132   // edge kernel k-major stride
#define SNT 66    // nodefused k-major stride

typedef unsigned long long u64;

// ---------------- scratch (device globals; no allocation) ----------------
__device__ float g_h[NND * HD];
__device__ float g_PA[NND * HD];
__device__ float g_PB[NND * HD];
__device__ float g_agg[NND * HD];
__device__ float g_radial[NE];
__device__ int   g_count[NND];
__device__ int   g_cursor[NND];
__device__ int   g_rowS[NE];
__device__ int   g_colS[NE];
__device__ float g_radS[NE];
__device__ float g_mS[NE];

// fast silu: x*sigmoid(x) = 0.5x + 0.5x*tanh(0.5x)
__device__ __forceinline__ float silu(float x) {
    float h = 0.5f * x;
    float t;
    asm("tanh.approx.f32 %0, %1;" : "=f"(t) : "f"(h));
    return fmaf(h, t, h);
}

// ---- packed f32x2 helpers (sm_103a) ----
__device__ __forceinline__ u64 ffma2(u64 a, u64 b, u64 c) {
    u64 d;
    asm("fma.rn.f32x2 %0, %1, %2, %3;" : "=l"(d) : "l"(a), "l"(b), "l"(c));
    return d;
}
__device__ __forceinline__ u64 packdup(float x) {
    u64 d;
    unsigned int r = __float_as_uint(x);
    asm("mov.b64 %0, {%1, %2};" : "=l"(d) : "r"(r), "r"(r));
    return d;
}
__device__ __forceinline__ float2 unpk(u64 v) {
    float2 r;
    asm("mov.b64 {%0, %1}, %2;" : "=f"(r.x), "=f"(r.y) : "l"(v));
    return r;
}
union U16 { float4 f; u64 u[2]; float s[4]; };

// ================= setup 1: embedding + zero count =================
__global__ void k_su1(const float* __restrict__ h0,
                      const float* __restrict__ emb_w,
                      const float* __restrict__ emb_b) {
    int idx = blockIdx.x * blockDim.x + threadIdx.x;
    if (idx < NND) g_count[idx] = 0;
    int n = idx >> 6, j = idx & 63;
    float acc = emb_b[j];
#pragma unroll
    for (int f = 0; f < FIN; f++)
        acc += h0[n * FIN + f] * emb_w[f * HD + j];
    g_h[idx] = acc;
}

// ================= setup 2: precomp0 (blocks 0..511) | radial+hist (512..2431) =================
#define P0_SMEM (64 * 128 + 64 * 65 + 128)
__global__ __launch_bounds__(256)
void k_su2(const float* __restrict__ W1,
           const float* __restrict__ b1,
           const int* __restrict__ edges,
           const float* __restrict__ pos) {
    int tid = threadIdx.x;
    if (blockIdx.x >= 512) {
        int e = (blockIdx.x - 512) * 256 + tid;
        int r = edges[e], c = edges[NE + e];
        float dx = pos[r * 3 + 0] - pos[c * 3 + 0];
        float dy = pos[r * 3 + 1] - pos[c * 3 + 1];
        float dz = pos[r * 3 + 2] - pos[c * 3 + 2];
        g_radial[e] = dx * dx + dy * dy + dz * dz;
        atomicAdd(&g_count[r], 1);
        return;
    }
    extern __shared__ float sm[];
    float* sW = sm;
    float* sX = sm + 8192;
    float* sBp = sX + 64 * 65;
    int n0 = blockIdx.x * 64;

    for (int idx = tid; idx < 8192; idx += 256) {
        int k = idx >> 7, j = idx & 127;
        sW[idx] = (j < 64) ? W1[k * HD + j] : W1[(64 + k) * HD + (j - 64)];
    }
    for (int idx = tid; idx < 4096; idx += 256) {
        int n = idx >> 6, c = idx & 63;
        sX[n * 65 + c] = g_h[(n0 + n) * HD + c];
    }
    if (tid < 128) sBp[tid] = (tid < 64) ? b1[tid] : 0.f;
    __syncthreads();

    {
        float4 z = make_float4(0.f, 0.f, 0.f, 0.f);
        float4* a4 = (float4*)&g_agg[n0 * HD];
#pragma unroll
        for (int i = 0; i < 4; i++) a4[tid + 256 * i] = z;
    }

    int gn = tid >> 4, gj = tid & 15;
    int nb = gn * 4, jb = gj * 8;

    u64 acc[4][4];
    {
        U16 b0, b1v;
        b0.f = *(const float4*)(sBp + jb);
        b1v.f = *(const float4*)(sBp + jb + 4);
#pragma unroll
        for (int q = 0; q < 4; q++) {
            acc[q][0] = b0.u[0]; acc[q][1] = b0.u[1];
            acc[q][2] = b1v.u[0]; acc[q][3] = b1v.u[1];
        }
    }
#pragma unroll 4
    for (int k = 0; k < 64; k++) {
        U16 w0, w1;
        const float4* bp = (const float4*)(sW + k * 128 + jb);
        w0.f = bp[0]; w1.f = bp[1];
#pragma unroll
        for (int q = 0; q < 4; q++) {
            u64 a = packdup(sX[(nb + q) * 65 + k]);
            acc[q][0] = ffma2(a, w0.u[0], acc[q][0]);
            acc[q][1] = ffma2(a, w0.u[1], acc[q][1]);
            acc[q][2] = ffma2(a, w1.u[0], acc[q][2]);
            acc[q][3] = ffma2(a, w1.u[1], acc[q][3]);
        }
    }
    float* dst = (gj < 8) ? g_PA : g_PB;
    int col = (gj < 8) ? jb : (jb - 64);
#pragma unroll
    for (int q = 0; q < 4; q++) {
        U16 o0, o1;
        o0.u[0] = acc[q][0]; o0.u[1] = acc[q][1];
        o1.u[0] = acc[q][2]; o1.u[1] = acc[q][3];
        float4* d4 = (float4*)&dst[(n0 + nb + q) * HD + col];
        d4[0] = o0.f; d4[1] = o1.f;
    }
}

// ================= setup 3: scan (block 0) | zero pred (block 1) =================
__global__ __launch_bounds__(1024)
void k_su3(float* __restrict__ pred) {
    __shared__ int s[1024];
    int t = threadIdx.x;
    if (blockIdx.x == 1) {
        pred[t] = 0.f;   // NR == 1024
        return;
    }
    int base = t * 32;
    int loc[32];
    int sum = 0;
#pragma unroll
    for (int i = 0; i < 32; i++) {
        loc[i] = sum;
        sum += g_count[base + i];
    }
    s[t] = sum;
    __syncthreads();
    for (int off = 1; off < 1024; off <<= 1) {
        int v = (t >= off) ? s[t - off] : 0;
        __syncthreads();
        s[t] += v;
        __syncthreads();
    }
    int excl = s[t] - sum;
#pragma unroll
    for (int i = 0; i < 32; i++)
        g_cursor[base + i] = excl + loc[i];
}

// ================= scatter + prep sorted arrays =================
__global__ void k_scatterprep(const int* __restrict__ edges,
                              const float* __restrict__ emask) {
    int e = blockIdx.x * blockDim.x + threadIdx.x;
    if (e >= NE) return;
    int r = edges[e];
    int p = atomicAdd(&g_cursor[r], 1);
    g_rowS[p] = r;
    g_colS[p] = edges[NE + e];
    g_radS[p] = g_radial[e];
    g_mS[p]   = emask[e];
}

// ================= edge kernel core (R13 version) =================
#define EDGE_SMEM (4096 + 64 * SVT + 64 + 64 + TE + TE + TE + TE)
#define EDGE_META (4096 + 64 * SVT + 128)

__device__ __forceinline__ void edge_body(float* sm,
                                          const float* __restrict__ W2,
                                          const float* __restrict__ b2,
                                          const float* __restrict__ w1c) {
    float* sW  = sm;
    float* sVT = sm + 4096;
    float* sC  = sVT + 64 * SVT;
    float* sB  = sC + 64;
    int*   sR  = (int*)(sB + 64);
    int*   sCl = sR + TE;
    float* sRd = (float*)(sCl + TE);
    float* sM  = sRd + TE;
    int tid = threadIdx.x;

    {
        const float4* src = (const float4*)W2;
        float4* dst = (float4*)sW;
#pragma unroll
        for (int i = 0; i < 4; i++)
            dst[tid + 256 * i] = src[tid + 256 * i];
    }
    if (tid < 64) { sC[tid] = w1c[tid]; sB[tid] = b2[tid]; }
    __syncthreads();

    int lane = tid & 31, wid = tid >> 5;
    float c0 = sC[lane], c1 = sC[32 + lane];

#pragma unroll 4
    for (int i = 0; i < 16; i++) {
        int el = wid * 16 + i;
        int r = sR[el], c = sCl[el];
        float rad = sRd[el];
        float v0 = silu(g_PA[r * HD + lane]      + g_PB[c * HD + lane]      + rad * c0);
        float v1 = silu(g_PA[r * HD + 32 + lane] + g_PB[c * HD + 32 + lane] + rad * c1);
        sVT[lane * SVT + el]        = v0;
        sVT[(32 + lane) * SVT + el] = v1;
    }
    __syncthreads();

    int jb = wid * 8;
    int eb = lane * 4;

    u64 acc[4][4];
    {
        U16 bb0, bb1;
        bb0.f = *(const float4*)(sB + jb);
        bb1.f = *(const float4*)(sB + jb + 4);
#pragma unroll
        for (int q = 0; q < 4; q++) {
            acc[q][0] = bb0.u[0]; acc[q][1] = bb0.u[1];
            acc[q][2] = bb1.u[0]; acc[q][3] = bb1.u[1];
        }
    }
#pragma unroll 4
    for (int k = 0; k < 64; k++) {
        U16 w0, w1;
        const float4* bp = (const float4*)(sW + k * 64 + jb);
        w0.f = bp[0]; w1.f = bp[1];
        U16 v4;
        v4.f = *(const float4*)(sVT + k * SVT + eb);
#pragma unroll
        for (int q = 0; q < 4; q++) {
            u64 a = packdup(v4.s[q]);
            acc[q][0] = ffma2(a, w0.u[0], acc[q][0]);
            acc[q][1] = ffma2(a, w0.u[1], acc[q][1]);
            acc[q][2] = ffma2(a, w1.u[0], acc[q][2]);
            acc[q][3] = ffma2(a, w1.u[1], acc[q][3]);
        }
    }

    float run[8];
#pragma unroll
    for (int jj = 0; jj < 8; jj++) run[jj] = 0.f;
    int curR = sR[eb];
#pragma unroll
    for (int q = 0; q < 4; q++) {
        int r = sR[eb + q];
        float m = sM[eb + q];
        if (r != curR) {
            float4* b4 = (float4*)&g_agg[curR * HD + jb];
            atomicAdd(b4,     make_float4(run[0], run[1], run[2], run[3]));
            atomicAdd(b4 + 1, make_float4(run[4], run[5], run[6], run[7]));
#pragma unroll
            for (int jj = 0; jj < 8; jj++) run[jj] = 0.f;
            curR = r;
        }
#pragma unroll
        for (int jp = 0; jp < 4; jp++) {
            float2 p = unpk(acc[q][jp]);
            run[2 * jp]     += silu(p.x) * m;
            run[2 * jp + 1] += silu(p.y) * m;
        }
    }
    {
        float4* b4 = (float4*)&g_agg[curR * HD + jb];
        atomicAdd(b4,     make_float4(run[0], run[1], run[2], run[3]));
        atomicAdd(b4 + 1, make_float4(run[4], run[5], run[6], run[7]));
    }
}

__global__ __launch_bounds__(256)
void k_edge0(const int* __restrict__ edges,
             const float* __restrict__ emask,
             const float* __restrict__ W2,
             const float* __restrict__ b2,
             const float* __restrict__ w1c) {
    extern __shared__ float sm[];
    int tid = threadIdx.x;
    int base = blockIdx.x * TE;
    int*   sR  = (int*)(sm + EDGE_META);
    int*   sCl = sR + TE;
    float* sRd = (float*)(sCl + TE);
    float* sM  = sRd + TE;
    if (tid < TE) {
        int e = base + tid;
        sR[tid]  = edges[e];
        sCl[tid] = edges[NE + e];
        sRd[tid] = g_radial[e];
        sM[tid]  = emask[e];
    }
    edge_body(sm, W2, b2, w1c);
}

__global__ __launch_bounds__(256)
void k_edge(const float* __restrict__ W2,
            const float* __restrict__ b2,
            const float* __restrict__ w1c) {
    extern __shared__ float sm[];
    int tid = threadIdx.x;
    int base = blockIdx.x * TE;
    int*   sR  = (int*)(sm + EDGE_META);
    int*   sCl = sR + TE;
    float* sRd = (float*)(sCl + TE);
    float* sM  = sRd + TE;
    if (tid < TE) {
        sR[tid]  = g_rowS[base + tid];
        sCl[tid] = g_colS[base + tid];
        sRd[tid] = g_radS[base + tid];
        sM[tid]  = g_mS[base + tid];
    }
    edge_body(sm, W2, b2, w1c);
}

// ================= fused node + next-layer precomp (FZ folded, K=139) =================
#define NF_W1  0
#define NF_W2  8960
#define NF_XT  (8960 + 4096)
#define NF_TT  (NF_XT + 9176)
#define NF_B1  (NF_TT + 64 * SNT)
#define NF_B2  (NF_B1 + 64)
#define NF_BP  (NF_B2 + 64)
#define NF_SMEM (NF_BP + 128)

__global__ __launch_bounds__(256)
void k_nodefused(const float* __restrict__ h0,
                 const float* __restrict__ W1n,
                 const float* __restrict__ b1n,
                 const float* __restrict__ W2n,
                 const float* __restrict__ b2n,
                 const float* __restrict__ Wp,
                 const float* __restrict__ bp,
                 int last) {
    extern __shared__ float sm[];
    float* sW1 = sm + NF_W1;
    float* sW2 = sm + NF_W2;
    float* sXT = sm + NF_XT;
    float* sTT = sm + NF_TT;
    float* sB1 = sm + NF_B1;
    float* sB2 = sm + NF_B2;
    float* sBp = sm + NF_BP;
    float* sHT = sW1;
    float* sWp = sXT;

    int tid = threadIdx.x;
    int lane = tid & 31, wid = tid >> 5;
    int n0 = blockIdx.x * 64;

    {
        const float4* src = (const float4*)W1n;
        float4* dst = (float4*)sW1;
        for (int idx = tid; idx < 2224; idx += 256)
            dst[idx] = src[idx];
    }
    {
        const float4* src = (const float4*)W2n;
        float4* dst = (float4*)sW2;
#pragma unroll
        for (int i = 0; i < 4; i++)
            dst[tid + 256 * i] = src[tid + 256 * i];
    }
    for (int idx = tid; idx < 8192; idx += 256) {
        int n = idx >> 7, c = idx & 127;
        float v = (c < 64) ? g_h[(n0 + n) * HD + c]
                           : g_agg[(n0 + n) * HD + (c - 64)];
        sXT[c * SNT + n] = v;
    }
    for (int idx = tid; idx < FIN * 64; idx += 256) {
        int c0 = idx >> 6, n = idx & 63;
        sXT[(128 + c0) * SNT + n] = h0[(n0 + n) * FIN + c0];
    }
    if (tid < 64) { sB1[tid] = b1n[tid]; sB2[tid] = b2n[tid]; }
    if (tid < 128) sBp[tid] = (!last && tid < 64) ? bp[tid] : 0.f;
    __syncthreads();

    if (!last) {
        float4 z = make_float4(0.f, 0.f, 0.f, 0.f);
        float4* a4 = (float4*)&g_agg[n0 * HD];
#pragma unroll
        for (int i = 0; i < 4; i++) a4[tid + 256 * i] = z;
    }

    int jb = wid * 8;
    int na = 2 * lane;

    // ---- GEMM1: t = silu(X@W1 + b1), K = 139 ----
    u64 acc[2][4];
    {
        U16 b0, b1v;
        b0.f  = *(const float4*)(sB1 + jb);
        b1v.f = *(const float4*)(sB1 + jb + 4);
#pragma unroll
        for (int q = 0; q < 2; q++) {
            acc[q][0] = b0.u[0]; acc[q][1] = b0.u[1];
            acc[q][2] = b1v.u[0]; acc[q][3] = b1v.u[1];
        }
    }
#pragma unroll 4
    for (int k = 0; k < NINC; k++) {
        U16 w0, w1;
        const float4* wp4 = (const float4*)(sW1 + k * 64 + jb);
        w0.f = wp4[0]; w1.f = wp4[1];
        float2 x = *(const float2*)(sXT + k * SNT + na);
        u64 a0 = packdup(x.x), a1 = packdup(x.y);
        acc[0][0] = ffma2(a0, w0.u[0], acc[0][0]);
        acc[0][1] = ffma2(a0, w0.u[1], acc[0][1]);
        acc[0][2] = ffma2(a0, w1.u[0], acc[0][2]);
        acc[0][3] = ffma2(a0, w1.u[1], acc[0][3]);
        acc[1][0] = ffma2(a1, w0.u[0], acc[1][0]);
        acc[1][1] = ffma2(a1, w0.u[1], acc[1][1]);
        acc[1][2] = ffma2(a1, w1.u[0], acc[1][2]);
        acc[1][3] = ffma2(a1, w1.u[1], acc[1][3]);
    }
    {
        float t0[8], t1[8];
#pragma unroll
        for (int p = 0; p < 4; p++) {
            float2 a = unpk(acc[0][p]);
            float2 b = unpk(acc[1][p]);
            t0[2 * p] = silu(a.x); t0[2 * p + 1] = silu(a.y);
            t1[2 * p] = silu(b.x); t1[2 * p + 1] = silu(b.y);
        }
#pragma unroll
        for (int jj = 0; jj < 8; jj++)
            *(float2*)(sTT + (jb + jj) * SNT + na) = make_float2(t0[jj], t1[jj]);
    }
    __syncthreads();

    if (!last) {
        for (int idx = tid; idx < 8192; idx += 256) {
            int k = idx >> 7, j = idx & 127;
            sWp[k * 128 + j] = (j < 64) ? Wp[k * HD + j]
                                        : Wp[(64 + k) * HD + (j - 64)];
        }
    }

    // ---- GEMM2: h' = t@W2 + b2 ----
    u64 acc2[2][4];
    {
        U16 b0, b1v;
        b0.f  = *(const float4*)(sB2 + jb);
        b1v.f = *(const float4*)(sB2 + jb + 4);
#pragma unroll
        for (int q = 0; q < 2; q++) {
            acc2[q][0] = b0.u[0]; acc2[q][1] = b0.u[1];
            acc2[q][2] = b1v.u[0]; acc2[q][3] = b1v.u[1];
        }
    }
#pragma unroll 4
    for (int k = 0; k < 64; k++) {
        U16 w0, w1;
        const float4* wp4 = (const float4*)(sW2 + k * 64 + jb);
        w0.f = wp4[0]; w1.f = wp4[1];
        float2 x = *(const float2*)(sTT + k * SNT + na);
        u64 a0 = packdup(x.x), a1 = packdup(x.y);
        acc2[0][0] = ffma2(a0, w0.u[0], acc2[0][0]);
        acc2[0][1] = ffma2(a0, w0.u[1], acc2[0][1]);
        acc2[0][2] = ffma2(a0, w1.u[0], acc2[0][2]);
        acc2[0][3] = ffma2(a0, w1.u[1], acc2[0][3]);
        acc2[1][0] = ffma2(a1, w0.u[0], acc2[1][0]);
        acc2[1][1] = ffma2(a1, w0.u[1], acc2[1][1]);
        acc2[1][2] = ffma2(a1, w1.u[0], acc2[1][2]);
        acc2[1][3] = ffma2(a1, w1.u[1], acc2[1][3]);
    }
#pragma unroll
    for (int q = 0; q < 2; q++) {
        U16 o0, o1;
        o0.u[0] = acc2[q][0]; o0.u[1] = acc2[q][1];
        o1.u[0] = acc2[q][2]; o1.u[1] = acc2[q][3];
        float4* d4 = (float4*)&g_h[(n0 + na + q) * HD + jb];
        d4[0] = o0.f; d4[1] = o1.f;
    }
    if (last) return;
    {
        float h0v[8], h1v[8];
#pragma unroll
        for (int p = 0; p < 4; p++) {
            float2 a = unpk(acc2[0][p]);
            float2 b = unpk(acc2[1][p]);
            h0v[2 * p] = a.x; h0v[2 * p + 1] = a.y;
            h1v[2 * p] = b.x; h1v[2 * p + 1] = b.y;
        }
#pragma unroll
        for (int jj = 0; jj < 8; jj++)
            *(float2*)(sHT + (jb + jj) * SNT + na) = make_float2(h0v[jj], h1v[jj]);
    }
    __syncthreads();

    // ---- GEMM3: [PA|PB]_{l+1} = h'@Wp + [b1p|0], warp owns 16 cols ----
    int jb3 = wid * 16;
    u64 acc3[2][8];
    {
        U16 b4[4];
#pragma unroll
        for (int i = 0; i < 4; i++)
            b4[i].f = *(const float4*)(sBp + jb3 + 4 * i);
#pragma unroll
        for (int q = 0; q < 2; q++)
#pragma unroll
            for (int i = 0; i < 4; i++) {
                acc3[q][2 * i]     = b4[i].u[0];
                acc3[q][2 * i + 1] = b4[i].u[1];
            }
    }
#pragma unroll 2
    for (int k = 0; k < 64; k++) {
        U16 w[4];
        const float4* wp4 = (const float4*)(sWp + k * 128 + jb3);
#pragma unroll
        for (int i = 0; i < 4; i++) w[i].f = wp4[i];
        float2 x = *(const float2*)(sHT + k * SNT + na);
        u64 a0 = packdup(x.x), a1 = packdup(x.y);
#pragma unroll
        for (int i = 0; i < 4; i++) {
            acc3[0][2 * i]     = ffma2(a0, w[i].u[0], acc3[0][2 * i]);
            acc3[0][2 * i + 1] = ffma2(a0, w[i].u[1], acc3[0][2 * i + 1]);
            acc3[1][2 * i]     = ffma2(a1, w[i].u[0], acc3[1][2 * i]);
            acc3[1][2 * i + 1] = ffma2(a1, w[i].u[1], acc3[1][2 * i + 1]);
        }
    }
    {
        float* dst = (jb3 < 64) ? g_PA : g_PB;
        int col = (jb3 < 64) ? jb3 : (jb3 - 64);
#pragma unroll
        for (int q = 0; q < 2; q++) {
            float4* d4 = (float4*)&dst[(n0 + na + q) * HD + col];
#pragma unroll
            for (int i = 0; i < 4; i++) {
                U16 o;
                o.u[0] = acc3[q][2 * i]; o.u[1] = acc3[q][2 * i + 1];
                d4[i] = o.f;
            }
        }
    }
}

// ================= final =================
#define FINAL_SMEM_FLOATS (4096 * 3 + 64 * 3 + 256)
__global__ void k_final(const float* __restrict__ nmask,
                        const float* __restrict__ dw1, const float* __restrict__ db1,
                        const float* __restrict__ dw2, const float* __restrict__ db2,
                        const float* __restrict__ gw1, const float* __restrict__ gb1,
                        const float* __restrict__ gw2, const float* __restrict__ gb2,
                        const int* __restrict__ ridx, const float* __restrict__ rsign,
                        float* __restrict__ pred) {
    extern __shared__ float sm[];
    float* sD1 = sm;
    float* sD2 = sm + 4096;
    float* sG1 = sm + 8192;
    float* sDB1 = sm + 12288;
    float* sDB2 = sDB1 + 64;
    float* sGB1 = sDB2 + 64;
    float* red  = sGB1 + 64;
    int tid = threadIdx.x;
    for (int idx = tid; idx < 4096; idx += blockDim.x) {
        int k = idx >> 6, j = idx & 63;
        int si = k * 64 + ((j & 31) << 1) + (j >> 5);
        sD1[si] = dw1[k * HD + j];
        sD2[si] = dw2[k * HD + j];
        sG1[si] = gw1[k * HD + j];
    }
    if (tid < 64) { sDB1[tid] = db1[tid]; sDB2[tid] = db2[tid]; sGB1[tid] = gb1[tid]; }
    __syncthreads();
    int lane = tid & 31, wid = tid >> 5;
    int g = blockIdx.x;
    const float2* D1 = (const float2*)sD1;
    const float2* D2 = (const float2*)sD2;
    const float2* G1 = (const float2*)sG1;
    float acc0 = 0.f, acc1 = 0.f;
#pragma unroll
    for (int i = 0; i < 4; i++) {
        int n = g * NPG + wid * 4 + i;
        float hl = g_h[n * HD + lane], hh = g_h[n * HD + 32 + lane];
        float t0 = sDB1[lane], t1 = sDB1[32 + lane];
#pragma unroll
        for (int k = 0; k < 32; k++) {
            float v = __shfl_sync(0xffffffffu, hl, k);
            float2 w = D1[k * 32 + lane];
            t0 += v * w.x; t1 += v * w.y;
        }
#pragma unroll
        for (int k = 0; k < 32; k++) {
            float v = __shfl_sync(0xffffffffu, hh, k);
            float2 w = D1[(32 + k) * 32 + lane];
            t0 += v * w.x; t1 += v * w.y;
        }
        t0 = silu(t0); t1 = silu(t1);
        float o0 = sDB2[lane], o1 = sDB2[32 + lane];
#pragma unroll
        for (int k = 0; k < 32; k++) {
            float v = __shfl_sync(0xffffffffu, t0, k);
            float2 w = D2[k * 32 + lane];
            o0 += v * w.x; o1 += v * w.y;
        }
#pragma unroll
        for (int k = 0; k < 32; k++) {
            float v = __shfl_sync(0xffffffffu, t1, k);
            float2 w = D2[(32 + k) * 32 + lane];
            o0 += v * w.x; o1 += v * w.y;
        }
        float m = nmask[n];
        acc0 += o0 * m; acc1 += o1 * m;
    }
    red[wid * 64 + lane] = acc0;
    red[wid * 64 + 32 + lane] = acc1;
    __syncthreads();
    if (wid == 0) {
        float hg0 = red[lane] + red[64 + lane] + red[128 + lane] + red[192 + lane];
        float hg1 = red[32 + lane] + red[96 + lane] + red[160 + lane] + red[224 + lane];
        float t0 = sGB1[lane], t1 = sGB1[32 + lane];
#pragma unroll
        for (int k = 0; k < 32; k++) {
            float v = __shfl_sync(0xffffffffu, hg0, k);
            float2 w = G1[k * 32 + lane];
            t0 += v * w.x; t1 += v * w.y;
        }
#pragma unroll
        for (int k = 0; k < 32; k++) {
            float v = __shfl_sync(0xffffffffu, hg1, k);
            float2 w = G1[(32 + k) * 32 + lane];
            t0 += v * w.x; t1 += v * w.y;
        }
        t0 = silu(t0); t1 = silu(t1);
        float part = t0 * gw2[lane] + t1 * gw2[32 + lane];
#pragma unroll
        for (int off = 16; off > 0; off >>= 1)
            part += __shfl_xor_sync(0xffffffffu, part, off);
        if (lane == 0) {
            float val = (part + gb2[0]) * rsign[g];
            atomicAdd(&pred[ridx[g]], val);
        }
    }
}

// ================= launch =================
extern "C" void kernel_launch(void* const* d_in, const int* in_sizes, int n_in,
                              void* d_out, int out_size) {
    const float* h0    = (const float*)d_in[0];
    const float* pos   = (const float*)d_in[1];
    const int*   edges = (const int*)  d_in[2];
    const float* nmask = (const float*)d_in[3];
    const float* emask = (const float*)d_in[4];
    const int*   ridx  = (const int*)  d_in[5];
    const float* rsign = (const float*)d_in[6];
    const float* emb_w = (const float*)d_in[7];
    const float* emb_b = (const float*)d_in[8];
    const float* ew1   = (const float*)d_in[9];
    const float* eb1   = (const float*)d_in[10];
    const float* ew2   = (const float*)d_in[11];
    const float* eb2   = (const float*)d_in[12];
    const float* nw1   = (const float*)d_in[13];
    const float* nb1   = (const float*)d_in[14];
    const float* nw2   = (const float*)d_in[15];
    const float* nb2   = (const float*)d_in[16];
    const float* dw1   = (const float*)d_in[17];
    const float* db1   = (const float*)d_in[18];
    const float* dw2   = (const float*)d_in[19];
    const float* db2   = (const float*)d_in[20];
    const float* gw1   = (const float*)d_in[21];
    const float* gb1   = (const float*)d_in[22];
    const float* gw2   = (const float*)d_in[23];
    const float* gb2   = (const float*)d_in[24];
    float* pred = (float*)d_out;

    cudaFuncSetAttribute(k_su2, cudaFuncAttributeMaxDynamicSharedMemorySize,
                         P0_SMEM * 4);
    cudaFuncSetAttribute(k_edge0, cudaFuncAttributeMaxDynamicSharedMemorySize,
                         EDGE_SMEM * 4);
    cudaFuncSetAttribute(k_edge, cudaFuncAttributeMaxDynamicSharedMemorySize,
                         EDGE_SMEM * 4);
    cudaFuncSetAttribute(k_nodefused, cudaFuncAttributeMaxDynamicSharedMemorySize,
                         NF_SMEM * 4);
    cudaFuncSetAttribute(k_final, cudaFuncAttributeMaxDynamicSharedMemorySize,
                         FINAL_SMEM_FLOATS * 4);

    // L1: embedding + zero counts
    k_su1<<<NND * HD / 256, 256>>>(h0, emb_w, emb_b);
    // L2: precomp0 (512 blocks) | radial+hist (1920 blocks)
    k_su2<<<512 + 1920, 256, P0_SMEM * 4>>>(ew1, eb1, edges, pos);
    // L3: scan (1) | zero pred (1)
    k_su3<<<2, 1024>>>(pred);
    // L4: layer-0 edge, unsorted  <-- profiled slot
    k_edge0<<<NE / TE, 256, EDGE_SMEM * 4>>>(edges, emask, ew2, eb2,
                                             ew1 + 128 * HD);
    // L5: build sorted edge arrays for layers 1..3
    k_scatterprep<<<(NE + 255) / 256, 256>>>(edges, emask);

    for (int l = 0; l < NL; l++) {
        int last = (l == NL - 1);
        k_nodefused<<<NND / 64, 256, NF_SMEM * 4>>>(
            h0,
            nw1 + l * NINC * HD, nb1 + l * HD,
            nw2 + l * HD * HD, nb2 + l * HD,
            last ? (const float*)0 : (ew1 + (l + 1) * EINC * HD),
            last ? (const float*)0 : (eb1 + (l + 1) * HD),
            last);
        if (!last) {
            k_edge<<<NE / TE, 256, EDGE_SMEM * 4>>>(
                ew2 + (l + 1) * HD * HD, eb2 + (l + 1) * HD,
                ew1 + (l + 1) * EINC * HD + 128 * HD);
        }
    }

    k_final<<<NG, 128, FINAL_SMEM_FLOATS * 4>>>(
        nmask, dw1, db1, dw2, db2, gw1, gb1, gw2, gb2, ridx, rsign, pred);
}

// round 16
// speedup vs baseline: 1.3518x; 1.3518x over previous
#include <cuda_runtime.h>
#include <cstdint>

#define NND 32768
#define NE  491520
#define FIN 11
#define HD  64
#define NG  2048
#define NPG 16
#define NR  1024
#define NL  4
#define EINC 129
#define NINC 139
#define TE  128
#define SVT 132   // edge kernel k-major stride
#define SNT 66    // nodefused k-major stride

typedef unsigned long long u64;

// ---------------- scratch (device globals; no allocation) ----------------
__device__ float g_h[NND * HD];
__device__ float g_PA[NND * HD];
__device__ float g_PB[NND * HD];
__device__ float g_agg[NND * HD];
__device__ float g_radial[NE];
__device__ int   g_count[NND];
__device__ int   g_cursor[NND];
__device__ int   g_rowS[NE];
__device__ int   g_colS[NE];
__device__ float g_radS[NE];
__device__ float g_mS[NE];

// fast silu: x*sigmoid(x) = 0.5x + 0.5x*tanh(0.5x)
__device__ __forceinline__ float silu(float x) {
    float h = 0.5f * x;
    float t;
    asm("tanh.approx.f32 %0, %1;" : "=f"(t) : "f"(h));
    return fmaf(h, t, h);
}

// ---- packed f32x2 helpers (sm_103a) ----
__device__ __forceinline__ u64 ffma2(u64 a, u64 b, u64 c) {
    u64 d;
    asm("fma.rn.f32x2 %0, %1, %2, %3;" : "=l"(d) : "l"(a), "l"(b), "l"(c));
    return d;
}
__device__ __forceinline__ u64 packdup(float x) {
    u64 d;
    unsigned int r = __float_as_uint(x);
    asm("mov.b64 %0, {%1, %2};" : "=l"(d) : "r"(r), "r"(r));
    return d;
}
__device__ __forceinline__ float2 unpk(u64 v) {
    float2 r;
    asm("mov.b64 {%0, %1}, %2;" : "=f"(r.x), "=f"(r.y) : "l"(v));
    return r;
}
union U16 { float4 f; u64 u[2]; float s[4]; };

// ================= setup 1: embedding + zero count =================
__global__ void k_su1(const float* __restrict__ h0,
                      const float* __restrict__ emb_w,
                      const float* __restrict__ emb_b) {
    int idx = blockIdx.x * blockDim.x + threadIdx.x;
    if (idx < NND) g_count[idx] = 0;
    int n = idx >> 6, j = idx & 63;
    float acc = emb_b[j];
#pragma unroll
    for (int f = 0; f < FIN; f++)
        acc += h0[n * FIN + f] * emb_w[f * HD + j];
    g_h[idx] = acc;
}

// ================= setup 2: precomp0 (blocks 0..511) | radial+hist (512..2431) =================
#define P0_SMEM (64 * 128 + 64 * 65 + 128)
__global__ __launch_bounds__(256)
void k_su2(const float* __restrict__ W1,
           const float* __restrict__ b1,
           const int* __restrict__ edges,
           const float* __restrict__ pos) {
    int tid = threadIdx.x;
    if (blockIdx.x >= 512) {
        int e = (blockIdx.x - 512) * 256 + tid;
        int r = edges[e], c = edges[NE + e];
        float dx = pos[r * 3 + 0] - pos[c * 3 + 0];
        float dy = pos[r * 3 + 1] - pos[c * 3 + 1];
        float dz = pos[r * 3 + 2] - pos[c * 3 + 2];
        g_radial[e] = dx * dx + dy * dy + dz * dz;
        atomicAdd(&g_count[r], 1);
        return;
    }
    extern __shared__ float sm[];
    float* sW = sm;
    float* sX = sm + 8192;
    float* sBp = sX + 64 * 65;
    int n0 = blockIdx.x * 64;

    for (int idx = tid; idx < 8192; idx += 256) {
        int k = idx >> 7, j = idx & 127;
        sW[idx] = (j < 64) ? W1[k * HD + j] : W1[(64 + k) * HD + (j - 64)];
    }
    for (int idx = tid; idx < 4096; idx += 256) {
        int n = idx >> 6, c = idx & 63;
        sX[n * 65 + c] = g_h[(n0 + n) * HD + c];
    }
    if (tid < 128) sBp[tid] = (tid < 64) ? b1[tid] : 0.f;
    __syncthreads();

    {
        float4 z = make_float4(0.f, 0.f, 0.f, 0.f);
        float4* a4 = (float4*)&g_agg[n0 * HD];
#pragma unroll
        for (int i = 0; i < 4; i++) a4[tid + 256 * i] = z;
    }

    int gn = tid >> 4, gj = tid & 15;
    int nb = gn * 4, jb = gj * 8;

    u64 acc[4][4];
    {
        U16 b0, b1v;
        b0.f = *(const float4*)(sBp + jb);
        b1v.f = *(const float4*)(sBp + jb + 4);
#pragma unroll
        for (int q = 0; q < 4; q++) {
            acc[q][0] = b0.u[0]; acc[q][1] = b0.u[1];
            acc[q][2] = b1v.u[0]; acc[q][3] = b1v.u[1];
        }
    }
#pragma unroll 4
    for (int k = 0; k < 64; k++) {
        U16 w0, w1;
        const float4* bp = (const float4*)(sW + k * 128 + jb);
        w0.f = bp[0]; w1.f = bp[1];
#pragma unroll
        for (int q = 0; q < 4; q++) {
            u64 a = packdup(sX[(nb + q) * 65 + k]);
            acc[q][0] = ffma2(a, w0.u[0], acc[q][0]);
            acc[q][1] = ffma2(a, w0.u[1], acc[q][1]);
            acc[q][2] = ffma2(a, w1.u[0], acc[q][2]);
            acc[q][3] = ffma2(a, w1.u[1], acc[q][3]);
        }
    }
    float* dst = (gj < 8) ? g_PA : g_PB;
    int col = (gj < 8) ? jb : (jb - 64);
#pragma unroll
    for (int q = 0; q < 4; q++) {
        U16 o0, o1;
        o0.u[0] = acc[q][0]; o0.u[1] = acc[q][1];
        o1.u[0] = acc[q][2]; o1.u[1] = acc[q][3];
        float4* d4 = (float4*)&dst[(n0 + nb + q) * HD + col];
        d4[0] = o0.f; d4[1] = o1.f;
    }
}

// ================= setup 3: scan (block 0) | zero pred (block 1) =================
__global__ __launch_bounds__(1024)
void k_su3(float* __restrict__ pred) {
    __shared__ int s[1024];
    int t = threadIdx.x;
    if (blockIdx.x == 1) {
        pred[t] = 0.f;   // NR == 1024
        return;
    }
    int base = t * 32;
    int loc[32];
    int sum = 0;
#pragma unroll
    for (int i = 0; i < 32; i++) {
        loc[i] = sum;
        sum += g_count[base + i];
    }
    s[t] = sum;
    __syncthreads();
    for (int off = 1; off < 1024; off <<= 1) {
        int v = (t >= off) ? s[t - off] : 0;
        __syncthreads();
        s[t] += v;
        __syncthreads();
    }
    int excl = s[t] - sum;
#pragma unroll
    for (int i = 0; i < 32; i++)
        g_cursor[base + i] = excl + loc[i];
}

// ================= scatter + prep sorted arrays =================
__global__ void k_scatterprep(const int* __restrict__ edges,
                              const float* __restrict__ emask) {
    int e = blockIdx.x * blockDim.x + threadIdx.x;
    if (e >= NE) return;
    int r = edges[e];
    int p = atomicAdd(&g_cursor[r], 1);
    g_rowS[p] = r;
    g_colS[p] = edges[NE + e];
    g_radS[p] = g_radial[e];
    g_mS[p]   = emask[e];
}

// ================= edge kernel core =================
#define EDGE_SMEM (4096 + 64 * SVT + 64 + 64 + TE + TE + TE + TE)
#define EDGE_META (4096 + 64 * SVT + 128)

__device__ __forceinline__ void edge_body(float* sm,
                                          const float* __restrict__ W2,
                                          const float* __restrict__ b2,
                                          const float* __restrict__ w1c) {
    float* sW  = sm;
    float* sVT = sm + 4096;
    float* sC  = sVT + 64 * SVT;
    float* sB  = sC + 64;
    int*   sR  = (int*)(sB + 64);
    int*   sCl = sR + TE;
    float* sRd = (float*)(sCl + TE);
    float* sM  = sRd + TE;
    int tid = threadIdx.x;

    {
        const float4* src = (const float4*)W2;
        float4* dst = (float4*)sW;
#pragma unroll
        for (int i = 0; i < 4; i++)
            dst[tid + 256 * i] = src[tid + 256 * i];
    }
    if (tid < 64) { sC[tid] = w1c[tid]; sB[tid] = b2[tid]; }
    __syncthreads();

    int lane = tid & 31, wid = tid >> 5;
    float c0 = sC[lane], c1 = sC[32 + lane];

#pragma unroll 4
    for (int i = 0; i < 16; i++) {
        int el = wid * 16 + i;
        int r = sR[el], c = sCl[el];
        float rad = sRd[el];
        float v0 = silu(g_PA[r * HD + lane]      + g_PB[c * HD + lane]      + rad * c0);
        float v1 = silu(g_PA[r * HD + 32 + lane] + g_PB[c * HD + 32 + lane] + rad * c1);
        sVT[lane * SVT + el]        = v0;
        sVT[(32 + lane) * SVT + el] = v1;
    }
    __syncthreads();

    int jb = wid * 8;
    int eb = lane * 4;

    u64 acc[4][4];
    {
        U16 bb0, bb1;
        bb0.f = *(const float4*)(sB + jb);
        bb1.f = *(const float4*)(sB + jb + 4);
#pragma unroll
        for (int q = 0; q < 4; q++) {
            acc[q][0] = bb0.u[0]; acc[q][1] = bb0.u[1];
            acc[q][2] = bb1.u[0]; acc[q][3] = bb1.u[1];
        }
    }
#pragma unroll 4
    for (int k = 0; k < 64; k++) {
        U16 w0, w1;
        const float4* bp = (const float4*)(sW + k * 64 + jb);
        w0.f = bp[0]; w1.f = bp[1];
        U16 v4;
        v4.f = *(const float4*)(sVT + k * SVT + eb);
#pragma unroll
        for (int q = 0; q < 4; q++) {
            u64 a = packdup(v4.s[q]);
            acc[q][0] = ffma2(a, w0.u[0], acc[q][0]);
            acc[q][1] = ffma2(a, w0.u[1], acc[q][1]);
            acc[q][2] = ffma2(a, w1.u[0], acc[q][2]);
            acc[q][3] = ffma2(a, w1.u[1], acc[q][3]);
        }
    }

    float run[8];
#pragma unroll
    for (int jj = 0; jj < 8; jj++) run[jj] = 0.f;
    int curR = sR[eb];
#pragma unroll
    for (int q = 0; q < 4; q++) {
        int r = sR[eb + q];
        float m = sM[eb + q];
        if (r != curR) {
            float4* b4 = (float4*)&g_agg[curR * HD + jb];
            atomicAdd(b4,     make_float4(run[0], run[1], run[2], run[3]));
            atomicAdd(b4 + 1, make_float4(run[4], run[5], run[6], run[7]));
#pragma unroll
            for (int jj = 0; jj < 8; jj++) run[jj] = 0.f;
            curR = r;
        }
#pragma unroll
        for (int jp = 0; jp < 4; jp++) {
            float2 p = unpk(acc[q][jp]);
            run[2 * jp]     += silu(p.x) * m;
            run[2 * jp + 1] += silu(p.y) * m;
        }
    }
    {
        float4* b4 = (float4*)&g_agg[curR * HD + jb];
        atomicAdd(b4,     make_float4(run[0], run[1], run[2], run[3]));
        atomicAdd(b4 + 1, make_float4(run[4], run[5], run[6], run[7]));
    }
}

__global__ __launch_bounds__(256)
void k_edge0(const int* __restrict__ edges,
             const float* __restrict__ emask,
             const float* __restrict__ W2,
             const float* __restrict__ b2,
             const float* __restrict__ w1c) {
    extern __shared__ float sm[];
    int tid = threadIdx.x;
    int base = blockIdx.x * TE;
    int*   sR  = (int*)(sm + EDGE_META);
    int*   sCl = sR + TE;
    float* sRd = (float*)(sCl + TE);
    float* sM  = sRd + TE;
    if (tid < TE) {
        int e = base + tid;
        sR[tid]  = edges[e];
        sCl[tid] = edges[NE + e];
        sRd[tid] = g_radial[e];
        sM[tid]  = emask[e];
    }
    edge_body(sm, W2, b2, w1c);
}

__global__ __launch_bounds__(256)
void k_edge(const float* __restrict__ W2,
            const float* __restrict__ b2,
            const float* __restrict__ w1c) {
    extern __shared__ float sm[];
    int tid = threadIdx.x;
    int base = blockIdx.x * TE;
    int*   sR  = (int*)(sm + EDGE_META);
    int*   sCl = sR + TE;
    float* sRd = (float*)(sCl + TE);
    float* sM  = sRd + TE;
    if (tid < TE) {
        sR[tid]  = g_rowS[base + tid];
        sCl[tid] = g_colS[base + tid];
        sRd[tid] = g_radS[base + tid];
        sM[tid]  = g_mS[base + tid];
    }
    edge_body(sm, W2, b2, w1c);
}

// ================= fused node + next-layer precomp (FZ folded, K=139) =================
#define NF_W1  0
#define NF_W2  8960
#define NF_XT  (8960 + 4096)
#define NF_TT  (NF_XT + 9176)
#define NF_B1  (NF_TT + 64 * SNT)
#define NF_B2  (NF_B1 + 64)
#define NF_BP  (NF_B2 + 64)
#define NF_SMEM (NF_BP + 128)

__global__ __launch_bounds__(256)
void k_nodefused(const float* __restrict__ h0,
                 const float* __restrict__ W1n,
                 const float* __restrict__ b1n,
                 const float* __restrict__ W2n,
                 const float* __restrict__ b2n,
                 const float* __restrict__ Wp,
                 const float* __restrict__ bp,
                 int last) {
    extern __shared__ float sm[];
    float* sW1 = sm + NF_W1;
    float* sW2 = sm + NF_W2;
    float* sXT = sm + NF_XT;
    float* sTT = sm + NF_TT;
    float* sB1 = sm + NF_B1;
    float* sB2 = sm + NF_B2;
    float* sBp = sm + NF_BP;
    float* sHT = sW1;
    float* sWp = sXT;

    int tid = threadIdx.x;
    int lane = tid & 31, wid = tid >> 5;
    int n0 = blockIdx.x * 64;

    {
        const float4* src = (const float4*)W1n;
        float4* dst = (float4*)sW1;
        for (int idx = tid; idx < 2224; idx += 256)
            dst[idx] = src[idx];
    }
    {
        const float4* src = (const float4*)W2n;
        float4* dst = (float4*)sW2;
#pragma unroll
        for (int i = 0; i < 4; i++)
            dst[tid + 256 * i] = src[tid + 256 * i];
    }
    for (int idx = tid; idx < 8192; idx += 256) {
        int n = idx >> 7, c = idx & 127;
        float v = (c < 64) ? g_h[(n0 + n) * HD + c]
                           : g_agg[(n0 + n) * HD + (c - 64)];
        sXT[c * SNT + n] = v;
    }
    for (int idx = tid; idx < FIN * 64; idx += 256) {
        int c0 = idx >> 6, n = idx & 63;
        sXT[(128 + c0) * SNT + n] = h0[(n0 + n) * FIN + c0];
    }
    if (tid < 64) { sB1[tid] = b1n[tid]; sB2[tid] = b2n[tid]; }
    if (tid < 128) sBp[tid] = (!last && tid < 64) ? bp[tid] : 0.f;
    __syncthreads();

    if (!last) {
        float4 z = make_float4(0.f, 0.f, 0.f, 0.f);
        float4* a4 = (float4*)&g_agg[n0 * HD];
#pragma unroll
        for (int i = 0; i < 4; i++) a4[tid + 256 * i] = z;
    }

    int jb = wid * 8;
    int na = 2 * lane;

    // ---- GEMM1: t = silu(X@W1 + b1), K = 139 ----
    u64 acc[2][4];
    {
        U16 b0, b1v;
        b0.f  = *(const float4*)(sB1 + jb);
        b1v.f = *(const float4*)(sB1 + jb + 4);
#pragma unroll
        for (int q = 0; q < 2; q++) {
            acc[q][0] = b0.u[0]; acc[q][1] = b0.u[1];
            acc[q][2] = b1v.u[0]; acc[q][3] = b1v.u[1];
        }
    }
#pragma unroll 4
    for (int k = 0; k < NINC; k++) {
        U16 w0, w1;
        const float4* wp4 = (const float4*)(sW1 + k * 64 + jb);
        w0.f = wp4[0]; w1.f = wp4[1];
        float2 x = *(const float2*)(sXT + k * SNT + na);
        u64 a0 = packdup(x.x), a1 = packdup(x.y);
        acc[0][0] = ffma2(a0, w0.u[0], acc[0][0]);
        acc[0][1] = ffma2(a0, w0.u[1], acc[0][1]);
        acc[0][2] = ffma2(a0, w1.u[0], acc[0][2]);
        acc[0][3] = ffma2(a0, w1.u[1], acc[0][3]);
        acc[1][0] = ffma2(a1, w0.u[0], acc[1][0]);
        acc[1][1] = ffma2(a1, w0.u[1], acc[1][1]);
        acc[1][2] = ffma2(a1, w1.u[0], acc[1][2]);
        acc[1][3] = ffma2(a1, w1.u[1], acc[1][3]);
    }
    {
        float t0[8], t1[8];
#pragma unroll
        for (int p = 0; p < 4; p++) {
            float2 a = unpk(acc[0][p]);
            float2 b = unpk(acc[1][p]);
            t0[2 * p] = silu(a.x); t0[2 * p + 1] = silu(a.y);
            t1[2 * p] = silu(b.x); t1[2 * p + 1] = silu(b.y);
        }
#pragma unroll
        for (int jj = 0; jj < 8; jj++)
            *(float2*)(sTT + (jb + jj) * SNT + na) = make_float2(t0[jj], t1[jj]);
    }
    __syncthreads();

    if (!last) {
        for (int idx = tid; idx < 8192; idx += 256) {
            int k = idx >> 7, j = idx & 127;
            sWp[k * 128 + j] = (j < 64) ? Wp[k * HD + j]
                                        : Wp[(64 + k) * HD + (j - 64)];
        }
    }

    // ---- GEMM2: h' = t@W2 + b2 ----
    u64 acc2[2][4];
    {
        U16 b0, b1v;
        b0.f  = *(const float4*)(sB2 + jb);
        b1v.f = *(const float4*)(sB2 + jb + 4);
#pragma unroll
        for (int q = 0; q < 2; q++) {
            acc2[q][0] = b0.u[0]; acc2[q][1] = b0.u[1];
            acc2[q][2] = b1v.u[0]; acc2[q][3] = b1v.u[1];
        }
    }
#pragma unroll 4
    for (int k = 0; k < 64; k++) {
        U16 w0, w1;
        const float4* wp4 = (const float4*)(sW2 + k * 64 + jb);
        w0.f = wp4[0]; w1.f = wp4[1];
        float2 x = *(const float2*)(sTT + k * SNT + na);
        u64 a0 = packdup(x.x), a1 = packdup(x.y);
        acc2[0][0] = ffma2(a0, w0.u[0], acc2[0][0]);
        acc2[0][1] = ffma2(a0, w0.u[1], acc2[0][1]);
        acc2[0][2] = ffma2(a0, w1.u[0], acc2[0][2]);
        acc2[0][3] = ffma2(a0, w1.u[1], acc2[0][3]);
        acc2[1][0] = ffma2(a1, w0.u[0], acc2[1][0]);
        acc2[1][1] = ffma2(a1, w0.u[1], acc2[1][1]);
        acc2[1][2] = ffma2(a1, w1.u[0], acc2[1][2]);
        acc2[1][3] = ffma2(a1, w1.u[1], acc2[1][3]);
    }
#pragma unroll
    for (int q = 0; q < 2; q++) {
        U16 o0, o1;
        o0.u[0] = acc2[q][0]; o0.u[1] = acc2[q][1];
        o1.u[0] = acc2[q][2]; o1.u[1] = acc2[q][3];
        float4* d4 = (float4*)&g_h[(n0 + na + q) * HD + jb];
        d4[0] = o0.f; d4[1] = o1.f;
    }
    if (last) return;
    {
        float h0v[8], h1v[8];
#pragma unroll
        for (int p = 0; p < 4; p++) {
            float2 a = unpk(acc2[0][p]);
            float2 b = unpk(acc2[1][p]);
            h0v[2 * p] = a.x; h0v[2 * p + 1] = a.y;
            h1v[2 * p] = b.x; h1v[2 * p + 1] = b.y;
        }
#pragma unroll
        for (int jj = 0; jj < 8; jj++)
            *(float2*)(sHT + (jb + jj) * SNT + na) = make_float2(h0v[jj], h1v[jj]);
    }
    __syncthreads();

    // ---- GEMM3: [PA|PB]_{l+1} = h'@Wp + [b1p|0], warp owns 16 cols ----
    int jb3 = wid * 16;
    u64 acc3[2][8];
    {
        U16 b4[4];
#pragma unroll
        for (int i = 0; i < 4; i++)
            b4[i].f = *(const float4*)(sBp + jb3 + 4 * i);
#pragma unroll
        for (int q = 0; q < 2; q++)
#pragma unroll
            for (int i = 0; i < 4; i++) {
                acc3[q][2 * i]     = b4[i].u[0];
                acc3[q][2 * i + 1] = b4[i].u[1];
            }
    }
#pragma unroll 2
    for (int k = 0; k < 64; k++) {
        U16 w[4];
        const float4* wp4 = (const float4*)(sWp + k * 128 + jb3);
#pragma unroll
        for (int i = 0; i < 4; i++) w[i].f = wp4[i];
        float2 x = *(const float2*)(sHT + k * SNT + na);
        u64 a0 = packdup(x.x), a1 = packdup(x.y);
#pragma unroll
        for (int i = 0; i < 4; i++) {
            acc3[0][2 * i]     = ffma2(a0, w[i].u[0], acc3[0][2 * i]);
            acc3[0][2 * i + 1] = ffma2(a0, w[i].u[1], acc3[0][2 * i + 1]);
            acc3[1][2 * i]     = ffma2(a1, w[i].u[0], acc3[1][2 * i]);
            acc3[1][2 * i + 1] = ffma2(a1, w[i].u[1], acc3[1][2 * i + 1]);
        }
    }
    {
        float* dst = (jb3 < 64) ? g_PA : g_PB;
        int col = (jb3 < 64) ? jb3 : (jb3 - 64);
#pragma unroll
        for (int q = 0; q < 2; q++) {
            float4* d4 = (float4*)&dst[(n0 + na + q) * HD + col];
#pragma unroll
            for (int i = 0; i < 4; i++) {
                U16 o;
                o.u[0] = acc3[q][2 * i]; o.u[1] = acc3[q][2 * i + 1];
                d4[i] = o.f;
            }
        }
    }
}

// ================= final =================
#define FINAL_SMEM_FLOATS (4096 * 3 + 64 * 3 + 256)
__global__ void k_final(const float* __restrict__ nmask,
                        const float* __restrict__ dw1, const float* __restrict__ db1,
                        const float* __restrict__ dw2, const float* __restrict__ db2,
                        const float* __restrict__ gw1, const float* __restrict__ gb1,
                        const float* __restrict__ gw2, const float* __restrict__ gb2,
                        const int* __restrict__ ridx, const float* __restrict__ rsign,
                        float* __restrict__ pred) {
    extern __shared__ float sm[];
    float* sD1 = sm;
    float* sD2 = sm + 4096;
    float* sG1 = sm + 8192;
    float* sDB1 = sm + 12288;
    float* sDB2 = sDB1 + 64;
    float* sGB1 = sDB2 + 64;
    float* red  = sGB1 + 64;
    int tid = threadIdx.x;
    for (int idx = tid; idx < 4096; idx += blockDim.x) {
        int k = idx >> 6, j = idx & 63;
        int si = k * 64 + ((j & 31) << 1) + (j >> 5);
        sD1[si] = dw1[k * HD + j];
        sD2[si] = dw2[k * HD + j];
        sG1[si] = gw1[k * HD + j];
    }
    if (tid < 64) { sDB1[tid] = db1[tid]; sDB2[tid] = db2[tid]; sGB1[tid] = gb1[tid]; }
    __syncthreads();
    int lane = tid & 31, wid = tid >> 5;
    int g = blockIdx.x;
    const float2* D1 = (const float2*)sD1;
    const float2* D2 = (const float2*)sD2;
    const float2* G1 = (const float2*)sG1;
    float acc0 = 0.f, acc1 = 0.f;
#pragma unroll
    for (int i = 0; i < 4; i++) {
        int n = g * NPG + wid * 4 + i;
        float hl = g_h[n * HD + lane], hh = g_h[n * HD + 32 + lane];
        float t0 = sDB1[lane], t1 = sDB1[32 + lane];
#pragma unroll
        for (int k = 0; k < 32; k++) {
            float v = __shfl_sync(0xffffffffu, hl, k);
            float2 w = D1[k * 32 + lane];
            t0 += v * w.x; t1 += v * w.y;
        }
#pragma unroll
        for (int k = 0; k < 32; k++) {
            float v = __shfl_sync(0xffffffffu, hh, k);
            float2 w = D1[(32 + k) * 32 + lane];
            t0 += v * w.x; t1 += v * w.y;
        }
        t0 = silu(t0); t1 = silu(t1);
        float o0 = sDB2[lane], o1 = sDB2[32 + lane];
#pragma unroll
        for (int k = 0; k < 32; k++) {
            float v = __shfl_sync(0xffffffffu, t0, k);
            float2 w = D2[k * 32 + lane];
            o0 += v * w.x; o1 += v * w.y;
        }
#pragma unroll
        for (int k = 0; k < 32; k++) {
            float v = __shfl_sync(0xffffffffu, t1, k);
            float2 w = D2[(32 + k) * 32 + lane];
            o0 += v * w.x; o1 += v * w.y;
        }
        float m = nmask[n];
        acc0 += o0 * m; acc1 += o1 * m;
    }
    red[wid * 64 + lane] = acc0;
    red[wid * 64 + 32 + lane] = acc1;
    __syncthreads();
    if (wid == 0) {
        float hg0 = red[lane] + red[64 + lane] + red[128 + lane] + red[192 + lane];
        float hg1 = red[32 + lane] + red[96 + lane] + red[160 + lane] + red[224 + lane];
        float t0 = sGB1[lane], t1 = sGB1[32 + lane];
#pragma unroll
        for (int k = 0; k < 32; k++) {
            float v = __shfl_sync(0xffffffffu, hg0, k);
            float2 w = G1[k * 32 + lane];
            t0 += v * w.x; t1 += v * w.y;
        }
#pragma unroll
        for (int k = 0; k < 32; k++) {
            float v = __shfl_sync(0xffffffffu, hg1, k);
            float2 w = G1[(32 + k) * 32 + lane];
            t0 += v * w.x; t1 += v * w.y;
        }
        t0 = silu(t0); t1 = silu(t1);
        float part = t0 * gw2[lane] + t1 * gw2[32 + lane];
#pragma unroll
        for (int off = 16; off > 0; off >>= 1)
            part += __shfl_xor_sync(0xffffffffu, part, off);
        if (lane == 0) {
            float val = (part + gb2[0]) * rsign[g];
            atomicAdd(&pred[ridx[g]], val);
        }
    }
}

// ================= launch =================
extern "C" void kernel_launch(void* const* d_in, const int* in_sizes, int n_in,
                              void* d_out, int out_size) {
    const float* h0    = (const float*)d_in[0];
    const float* pos   = (const float*)d_in[1];
    const int*   edges = (const int*)  d_in[2];
    const float* nmask = (const float*)d_in[3];
    const float* emask = (const float*)d_in[4];
    const int*   ridx  = (const int*)  d_in[5];
    const float* rsign = (const float*)d_in[6];
    const float* emb_w = (const float*)d_in[7];
    const float* emb_b = (const float*)d_in[8];
    const float* ew1   = (const float*)d_in[9];
    const float* eb1   = (const float*)d_in[10];
    const float* ew2   = (const float*)d_in[11];
    const float* eb2   = (const float*)d_in[12];
    const float* nw1   = (const float*)d_in[13];
    const float* nb1   = (const float*)d_in[14];
    const float* nw2   = (const float*)d_in[15];
    const float* nb2   = (const float*)d_in[16];
    const float* dw1   = (const float*)d_in[17];
    const float* db1   = (const float*)d_in[18];
    const float* dw2   = (const float*)d_in[19];
    const float* db2   = (const float*)d_in[20];
    const float* gw1   = (const float*)d_in[21];
    const float* gb1   = (const float*)d_in[22];
    const float* gw2   = (const float*)d_in[23];
    const float* gb2   = (const float*)d_in[24];
    float* pred = (float*)d_out;

    cudaFuncSetAttribute(k_su2, cudaFuncAttributeMaxDynamicSharedMemorySize,
                         P0_SMEM * 4);
    cudaFuncSetAttribute(k_edge0, cudaFuncAttributeMaxDynamicSharedMemorySize,
                         EDGE_SMEM * 4);
    cudaFuncSetAttribute(k_edge, cudaFuncAttributeMaxDynamicSharedMemorySize,
                         EDGE_SMEM * 4);
    cudaFuncSetAttribute(k_nodefused, cudaFuncAttributeMaxDynamicSharedMemorySize,
                         NF_SMEM * 4);
    cudaFuncSetAttribute(k_final, cudaFuncAttributeMaxDynamicSharedMemorySize,
                         FINAL_SMEM_FLOATS * 4);

    // L1: embedding + zero counts
    k_su1<<<NND * HD / 256, 256>>>(h0, emb_w, emb_b);
    // L2: precomp0 (512 blocks) | radial+hist (1920 blocks)
    k_su2<<<512 + 1920, 256, P0_SMEM * 4>>>(ew1, eb1, edges, pos);
    // L3: scan (1) | zero pred (1)
    k_su3<<<2, 1024>>>(pred);
    // L4: layer-0 edge, unsorted  <-- profiled slot
    k_edge0<<<NE / TE, 256, EDGE_SMEM * 4>>>(edges, emask, ew2, eb2,
                                             ew1 + 128 * HD);
    // L5: build sorted edge arrays for layers 1..3
    k_scatterprep<<<(NE + 255) / 256, 256>>>(edges, emask);

    for (int l = 0; l < NL; l++) {
        int last = (l == NL - 1);
        k_nodefused<<<NND / 64, 256, NF_SMEM * 4>>>(
            h0,
            nw1 + l * NINC * HD, nb1 + l * HD,
            nw2 + l * HD * HD, nb2 + l * HD,
            last ? (const float*)0 : (ew1 + (l + 1) * EINC * HD),
            last ? (const float*)0 : (eb1 + (l + 1) * HD),
            last);
        if (!last) {
            k_edge<<<NE / TE, 256, EDGE_SMEM * 4>>>(
                ew2 + (l + 1) * HD * HD, eb2 + (l + 1) * HD,
                ew1 + (l + 1) * EINC * HD + 128 * HD);
        }
    }

    k_final<<<NG, 128, FINAL_SMEM_FLOATS * 4>>>(
        nmask, dw1, db1, dw2, db2, gw1, gb1, gw2, gb2, ridx, rsign, pred);
}

// round 17
// speedup vs baseline: 1.3979x; 1.0341x over previous
#include <cuda_runtime.h>
#include <cstdint>

#define NND 32768
#define NE  491520
#define FIN 11
#define HD  64
#define NG  2048
#define NPG 16
#define NR  1024
#define NL  4
#define EINC 129
#define NINC 139
#define TE  128
#define SVT 132   // edge kernel k-major stride
#define SNT 66    // nodefused k-major stride

typedef unsigned long long u64;

// ---------------- scratch (device globals; no allocation) ----------------
__device__ float g_h[NND * HD];
__device__ float g_PA[NND * HD];
__device__ float g_PB[NND * HD];
__device__ float g_agg[NND * HD];
__device__ float g_radial[NE];
__device__ int   g_count[NND];
__device__ int   g_cursor[NND];
__device__ int   g_rowS[NE];
__device__ int   g_colS[NE];
__device__ float g_radS[NE];
__device__ float g_mS[NE];

// fast silu: x*sigmoid(x) = 0.5x + 0.5x*tanh(0.5x)
__device__ __forceinline__ float silu(float x) {
    float h = 0.5f * x;
    float t;
    asm("tanh.approx.f32 %0, %1;" : "=f"(t) : "f"(h));
    return fmaf(h, t, h);
}

// ---- packed f32x2 helpers (sm_103a) ----
__device__ __forceinline__ u64 ffma2(u64 a, u64 b, u64 c) {
    u64 d;
    asm("fma.rn.f32x2 %0, %1, %2, %3;" : "=l"(d) : "l"(a), "l"(b), "l"(c));
    return d;
}
__device__ __forceinline__ u64 packdup(float x) {
    u64 d;
    unsigned int r = __float_as_uint(x);
    asm("mov.b64 %0, {%1, %2};" : "=l"(d) : "r"(r), "r"(r));
    return d;
}
__device__ __forceinline__ float2 unpk(u64 v) {
    float2 r;
    asm("mov.b64 {%0, %1}, %2;" : "=f"(r.x), "=f"(r.y) : "l"(v));
    return r;
}
union U16 { float4 f; u64 u[2]; float s[4]; };

// ================= setup 1: embedding + zero count =================
__global__ void k_su1(const float* __restrict__ h0,
                      const float* __restrict__ emb_w,
                      const float* __restrict__ emb_b) {
    int idx = blockIdx.x * blockDim.x + threadIdx.x;
    if (idx < NND) g_count[idx] = 0;
    int n = idx >> 6, j = idx & 63;
    float acc = emb_b[j];
#pragma unroll
    for (int f = 0; f < FIN; f++)
        acc += h0[n * FIN + f] * emb_w[f * HD + j];
    g_h[idx] = acc;
}

// ================= setup 2: precomp0 (blocks 0..511) | radial+hist (512..2431) =================
#define P0_SMEM (64 * 128 + 64 * 65 + 128)
__global__ __launch_bounds__(256)
void k_su2(const float* __restrict__ W1,
           const float* __restrict__ b1,
           const int* __restrict__ edges,
           const float* __restrict__ pos) {
    int tid = threadIdx.x;
    if (blockIdx.x >= 512) {
        int e = (blockIdx.x - 512) * 256 + tid;
        int r = edges[e], c = edges[NE + e];
        float dx = pos[r * 3 + 0] - pos[c * 3 + 0];
        float dy = pos[r * 3 + 1] - pos[c * 3 + 1];
        float dz = pos[r * 3 + 2] - pos[c * 3 + 2];
        g_radial[e] = dx * dx + dy * dy + dz * dz;
        atomicAdd(&g_count[r], 1);
        return;
    }
    extern __shared__ float sm[];
    float* sW = sm;
    float* sX = sm + 8192;
    float* sBp = sX + 64 * 65;
    int n0 = blockIdx.x * 64;

    for (int idx = tid; idx < 8192; idx += 256) {
        int k = idx >> 7, j = idx & 127;
        sW[idx] = (j < 64) ? W1[k * HD + j] : W1[(64 + k) * HD + (j - 64)];
    }
    for (int idx = tid; idx < 4096; idx += 256) {
        int n = idx >> 6, c = idx & 63;
        sX[n * 65 + c] = g_h[(n0 + n) * HD + c];
    }
    if (tid < 128) sBp[tid] = (tid < 64) ? b1[tid] : 0.f;
    __syncthreads();

    {
        float4 z = make_float4(0.f, 0.f, 0.f, 0.f);
        float4* a4 = (float4*)&g_agg[n0 * HD];
#pragma unroll
        for (int i = 0; i < 4; i++) a4[tid + 256 * i] = z;
    }

    int gn = tid >> 4, gj = tid & 15;
    int nb = gn * 4, jb = gj * 8;

    u64 acc[4][4];
    {
        U16 b0, b1v;
        b0.f = *(const float4*)(sBp + jb);
        b1v.f = *(const float4*)(sBp + jb + 4);
#pragma unroll
        for (int q = 0; q < 4; q++) {
            acc[q][0] = b0.u[0]; acc[q][1] = b0.u[1];
            acc[q][2] = b1v.u[0]; acc[q][3] = b1v.u[1];
        }
    }
#pragma unroll 4
    for (int k = 0; k < 64; k++) {
        U16 w0, w1;
        const float4* bp = (const float4*)(sW + k * 128 + jb);
        w0.f = bp[0]; w1.f = bp[1];
#pragma unroll
        for (int q = 0; q < 4; q++) {
            u64 a = packdup(sX[(nb + q) * 65 + k]);
            acc[q][0] = ffma2(a, w0.u[0], acc[q][0]);
            acc[q][1] = ffma2(a, w0.u[1], acc[q][1]);
            acc[q][2] = ffma2(a, w1.u[0], acc[q][2]);
            acc[q][3] = ffma2(a, w1.u[1], acc[q][3]);
        }
    }
    float* dst = (gj < 8) ? g_PA : g_PB;
    int col = (gj < 8) ? jb : (jb - 64);
#pragma unroll
    for (int q = 0; q < 4; q++) {
        U16 o0, o1;
        o0.u[0] = acc[q][0]; o0.u[1] = acc[q][1];
        o1.u[0] = acc[q][2]; o1.u[1] = acc[q][3];
        float4* d4 = (float4*)&dst[(n0 + nb + q) * HD + col];
        d4[0] = o0.f; d4[1] = o1.f;
    }
}

// ================= setup 3: scan (block 0) | zero pred (block 1) =================
__global__ __launch_bounds__(1024)
void k_su3(float* __restrict__ pred) {
    __shared__ int s[1024];
    int t = threadIdx.x;
    if (blockIdx.x == 1) {
        pred[t] = 0.f;   // NR == 1024
        return;
    }
    int base = t * 32;
    int loc[32];
    int sum = 0;
#pragma unroll
    for (int i = 0; i < 32; i++) {
        loc[i] = sum;
        sum += g_count[base + i];
    }
    s[t] = sum;
    __syncthreads();
    for (int off = 1; off < 1024; off <<= 1) {
        int v = (t >= off) ? s[t - off] : 0;
        __syncthreads();
        s[t] += v;
        __syncthreads();
    }
    int excl = s[t] - sum;
#pragma unroll
    for (int i = 0; i < 32; i++)
        g_cursor[base + i] = excl + loc[i];
}

// ================= scatter + prep sorted arrays =================
__global__ void k_scatterprep(const int* __restrict__ edges,
                              const float* __restrict__ emask) {
    int e = blockIdx.x * blockDim.x + threadIdx.x;
    if (e >= NE) return;
    int r = edges[e];
    int p = atomicAdd(&g_cursor[r], 1);
    g_rowS[p] = r;
    g_colS[p] = edges[NE + e];
    g_radS[p] = g_radial[e];
    g_mS[p]   = emask[e];
}

// ================= edge kernel: sorted edges, 2 tiles per CTA =================
#define EDGE_SMEM (4096 + 64 * SVT + 64 + 64 + TE + TE + TE + TE)
#define EDGE_META (4096 + 64 * SVT + 128)

__global__ __launch_bounds__(256)
void k_edge(const float* __restrict__ W2,
            const float* __restrict__ b2,
            const float* __restrict__ w1c) {
    extern __shared__ float sm[];
    float* sW  = sm;
    float* sVT = sm + 4096;
    float* sC  = sVT + 64 * SVT;
    float* sB  = sC + 64;
    int*   sR  = (int*)(sm + EDGE_META);
    int*   sCl = sR + TE;
    float* sRd = (float*)(sCl + TE);
    float* sM  = sRd + TE;
    int tid = threadIdx.x;
    int lane = tid & 31, wid = tid >> 5;

    {
        const float4* src = (const float4*)W2;
        float4* dst = (float4*)sW;
#pragma unroll
        for (int i = 0; i < 4; i++)
            dst[tid + 256 * i] = src[tid + 256 * i];
    }
    if (tid < 64) { sC[tid] = w1c[tid]; sB[tid] = b2[tid]; }

#pragma unroll
    for (int t = 0; t < 2; t++) {
        int base = (blockIdx.x * 2 + t) * TE;
        __syncthreads();   // W staged (t=0) / prev phase-3 meta reads done (t=1)
        if (tid < TE) {
            sR[tid]  = g_rowS[base + tid];
            sCl[tid] = g_colS[base + tid];
            sRd[tid] = g_radS[base + tid];
            sM[tid]  = g_mS[base + tid];
        }
        __syncthreads();

        float c0 = sC[lane], c1 = sC[32 + lane];

        // phase 1: v for TE edges (16 per warp); k-major stores
#pragma unroll 4
        for (int i = 0; i < 16; i++) {
            int el = wid * 16 + i;
            int r = sR[el], c = sCl[el];
            float rad = sRd[el];
            float v0 = silu(g_PA[r * HD + lane]      + g_PB[c * HD + lane]      + rad * c0);
            float v1 = silu(g_PA[r * HD + 32 + lane] + g_PB[c * HD + 32 + lane] + rad * c1);
            sVT[lane * SVT + el]        = v0;
            sVT[(32 + lane) * SVT + el] = v1;
        }
        __syncthreads();

        // phase 2: warp owns j-panel; lane owns 4 edges
        int jb = wid * 8;
        int eb = lane * 4;

        u64 acc[4][4];
        {
            U16 bb0, bb1;
            bb0.f = *(const float4*)(sB + jb);
            bb1.f = *(const float4*)(sB + jb + 4);
#pragma unroll
            for (int q = 0; q < 4; q++) {
                acc[q][0] = bb0.u[0]; acc[q][1] = bb0.u[1];
                acc[q][2] = bb1.u[0]; acc[q][3] = bb1.u[1];
            }
        }
#pragma unroll 4
        for (int k = 0; k < 64; k++) {
            U16 w0, w1;
            const float4* bp = (const float4*)(sW + k * 64 + jb);
            w0.f = bp[0]; w1.f = bp[1];
            U16 v4;
            v4.f = *(const float4*)(sVT + k * SVT + eb);
#pragma unroll
            for (int q = 0; q < 4; q++) {
                u64 a = packdup(v4.s[q]);
                acc[q][0] = ffma2(a, w0.u[0], acc[q][0]);
                acc[q][1] = ffma2(a, w0.u[1], acc[q][1]);
                acc[q][2] = ffma2(a, w1.u[0], acc[q][2]);
                acc[q][3] = ffma2(a, w1.u[1], acc[q][3]);
            }
        }

        // phase 3: silu, mask, run-length reduced vector atomics
        float run[8];
#pragma unroll
        for (int jj = 0; jj < 8; jj++) run[jj] = 0.f;
        int curR = sR[eb];
#pragma unroll
        for (int q = 0; q < 4; q++) {
            int r = sR[eb + q];
            float m = sM[eb + q];
            if (r != curR) {
                float4* b4 = (float4*)&g_agg[curR * HD + jb];
                atomicAdd(b4,     make_float4(run[0], run[1], run[2], run[3]));
                atomicAdd(b4 + 1, make_float4(run[4], run[5], run[6], run[7]));
#pragma unroll
                for (int jj = 0; jj < 8; jj++) run[jj] = 0.f;
                curR = r;
            }
#pragma unroll
            for (int jp = 0; jp < 4; jp++) {
                float2 p = unpk(acc[q][jp]);
                run[2 * jp]     += silu(p.x) * m;
                run[2 * jp + 1] += silu(p.y) * m;
            }
        }
        {
            float4* b4 = (float4*)&g_agg[curR * HD + jb];
            atomicAdd(b4,     make_float4(run[0], run[1], run[2], run[3]));
            atomicAdd(b4 + 1, make_float4(run[4], run[5], run[6], run[7]));
        }
    }
}

// ================= fused node + next-layer precomp (FZ folded, K=139) =================
#define NF_W1  0
#define NF_W2  8960
#define NF_XT  (8960 + 4096)
#define NF_TT  (NF_XT + 9176)
#define NF_B1  (NF_TT + 64 * SNT)
#define NF_B2  (NF_B1 + 64)
#define NF_BP  (NF_B2 + 64)
#define NF_SMEM (NF_BP + 128)

__global__ __launch_bounds__(256)
void k_nodefused(const float* __restrict__ h0,
                 const float* __restrict__ W1n,
                 const float* __restrict__ b1n,
                 const float* __restrict__ W2n,
                 const float* __restrict__ b2n,
                 const float* __restrict__ Wp,
                 const float* __restrict__ bp,
                 int last) {
    extern __shared__ float sm[];
    float* sW1 = sm + NF_W1;
    float* sW2 = sm + NF_W2;
    float* sXT = sm + NF_XT;
    float* sTT = sm + NF_TT;
    float* sB1 = sm + NF_B1;
    float* sB2 = sm + NF_B2;
    float* sBp = sm + NF_BP;
    float* sHT = sW1;
    float* sWp = sXT;

    int tid = threadIdx.x;
    int lane = tid & 31, wid = tid >> 5;
    int n0 = blockIdx.x * 64;

    {
        const float4* src = (const float4*)W1n;
        float4* dst = (float4*)sW1;
        for (int idx = tid; idx < 2224; idx += 256)
            dst[idx] = src[idx];
    }
    {
        const float4* src = (const float4*)W2n;
        float4* dst = (float4*)sW2;
#pragma unroll
        for (int i = 0; i < 4; i++)
            dst[tid + 256 * i] = src[tid + 256 * i];
    }
    for (int idx = tid; idx < 8192; idx += 256) {
        int n = idx >> 7, c = idx & 127;
        float v = (c < 64) ? g_h[(n0 + n) * HD + c]
                           : g_agg[(n0 + n) * HD + (c - 64)];
        sXT[c * SNT + n] = v;
    }
    for (int idx = tid; idx < FIN * 64; idx += 256) {
        int c0 = idx >> 6, n = idx & 63;
        sXT[(128 + c0) * SNT + n] = h0[(n0 + n) * FIN + c0];
    }
    if (tid < 64) { sB1[tid] = b1n[tid]; sB2[tid] = b2n[tid]; }
    if (tid < 128) sBp[tid] = (!last && tid < 64) ? bp[tid] : 0.f;
    __syncthreads();

    if (!last) {
        float4 z = make_float4(0.f, 0.f, 0.f, 0.f);
        float4* a4 = (float4*)&g_agg[n0 * HD];
#pragma unroll
        for (int i = 0; i < 4; i++) a4[tid + 256 * i] = z;
    }

    int jb = wid * 8;
    int na = 2 * lane;

    // ---- GEMM1: t = silu(X@W1 + b1), K = 139 ----
    u64 acc[2][4];
    {
        U16 b0, b1v;
        b0.f  = *(const float4*)(sB1 + jb);
        b1v.f = *(const float4*)(sB1 + jb + 4);
#pragma unroll
        for (int q = 0; q < 2; q++) {
            acc[q][0] = b0.u[0]; acc[q][1] = b0.u[1];
            acc[q][2] = b1v.u[0]; acc[q][3] = b1v.u[1];
        }
    }
#pragma unroll 4
    for (int k = 0; k < NINC; k++) {
        U16 w0, w1;
        const float4* wp4 = (const float4*)(sW1 + k * 64 + jb);
        w0.f = wp4[0]; w1.f = wp4[1];
        float2 x = *(const float2*)(sXT + k * SNT + na);
        u64 a0 = packdup(x.x), a1 = packdup(x.y);
        acc[0][0] = ffma2(a0, w0.u[0], acc[0][0]);
        acc[0][1] = ffma2(a0, w0.u[1], acc[0][1]);
        acc[0][2] = ffma2(a0, w1.u[0], acc[0][2]);
        acc[0][3] = ffma2(a0, w1.u[1], acc[0][3]);
        acc[1][0] = ffma2(a1, w0.u[0], acc[1][0]);
        acc[1][1] = ffma2(a1, w0.u[1], acc[1][1]);
        acc[1][2] = ffma2(a1, w1.u[0], acc[1][2]);
        acc[1][3] = ffma2(a1, w1.u[1], acc[1][3]);
    }
    {
        float t0[8], t1[8];
#pragma unroll
        for (int p = 0; p < 4; p++) {
            float2 a = unpk(acc[0][p]);
            float2 b = unpk(acc[1][p]);
            t0[2 * p] = silu(a.x); t0[2 * p + 1] = silu(a.y);
            t1[2 * p] = silu(b.x); t1[2 * p + 1] = silu(b.y);
        }
#pragma unroll
        for (int jj = 0; jj < 8; jj++)
            *(float2*)(sTT + (jb + jj) * SNT + na) = make_float2(t0[jj], t1[jj]);
    }
    __syncthreads();

    if (!last) {
        for (int idx = tid; idx < 8192; idx += 256) {
            int k = idx >> 7, j = idx & 127;
            sWp[k * 128 + j] = (j < 64) ? Wp[k * HD + j]
                                        : Wp[(64 + k) * HD + (j - 64)];
        }
    }

    // ---- GEMM2: h' = t@W2 + b2 ----
    u64 acc2[2][4];
    {
        U16 b0, b1v;
        b0.f  = *(const float4*)(sB2 + jb);
        b1v.f = *(const float4*)(sB2 + jb + 4);
#pragma unroll
        for (int q = 0; q < 2; q++) {
            acc2[q][0] = b0.u[0]; acc2[q][1] = b0.u[1];
            acc2[q][2] = b1v.u[0]; acc2[q][3] = b1v.u[1];
        }
    }
#pragma unroll 4
    for (int k = 0; k < 64; k++) {
        U16 w0, w1;
        const float4* wp4 = (const float4*)(sW2 + k * 64 + jb);
        w0.f = wp4[0]; w1.f = wp4[1];
        float2 x = *(const float2*)(sTT + k * SNT + na);
        u64 a0 = packdup(x.x), a1 = packdup(x.y);
        acc2[0][0] = ffma2(a0, w0.u[0], acc2[0][0]);
        acc2[0][1] = ffma2(a0, w0.u[1], acc2[0][1]);
        acc2[0][2] = ffma2(a0, w1.u[0], acc2[0][2]);
        acc2[0][3] = ffma2(a0, w1.u[1], acc2[0][3]);
        acc2[1][0] = ffma2(a1, w0.u[0], acc2[1][0]);
        acc2[1][1] = ffma2(a1, w0.u[1], acc2[1][1]);
        acc2[1][2] = ffma2(a1, w1.u[0], acc2[1][2]);
        acc2[1][3] = ffma2(a1, w1.u[1], acc2[1][3]);
    }
#pragma unroll
    for (int q = 0; q < 2; q++) {
        U16 o0, o1;
        o0.u[0] = acc2[q][0]; o0.u[1] = acc2[q][1];
        o1.u[0] = acc2[q][2]; o1.u[1] = acc2[q][3];
        float4* d4 = (float4*)&g_h[(n0 + na + q) * HD + jb];
        d4[0] = o0.f; d4[1] = o1.f;
    }
    if (last) return;
    {
        float h0v[8], h1v[8];
#pragma unroll
        for (int p = 0; p < 4; p++) {
            float2 a = unpk(acc2[0][p]);
            float2 b = unpk(acc2[1][p]);
            h0v[2 * p] = a.x; h0v[2 * p + 1] = a.y;
            h1v[2 * p] = b.x; h1v[2 * p + 1] = b.y;
        }
#pragma unroll
        for (int jj = 0; jj < 8; jj++)
            *(float2*)(sHT + (jb + jj) * SNT + na) = make_float2(h0v[jj], h1v[jj]);
    }
    __syncthreads();

    // ---- GEMM3: [PA|PB]_{l+1} = h'@Wp + [b1p|0], warp owns 16 cols ----
    int jb3 = wid * 16;
    u64 acc3[2][8];
    {
        U16 b4[4];
#pragma unroll
        for (int i = 0; i < 4; i++)
            b4[i].f = *(const float4*)(sBp + jb3 + 4 * i);
#pragma unroll
        for (int q = 0; q < 2; q++)
#pragma unroll
            for (int i = 0; i < 4; i++) {
                acc3[q][2 * i]     = b4[i].u[0];
                acc3[q][2 * i + 1] = b4[i].u[1];
            }
    }
#pragma unroll 2
    for (int k = 0; k < 64; k++) {
        U16 w[4];
        const float4* wp4 = (const float4*)(sWp + k * 128 + jb3);
#pragma unroll
        for (int i = 0; i < 4; i++) w[i].f = wp4[i];
        float2 x = *(const float2*)(sHT + k * SNT + na);
        u64 a0 = packdup(x.x), a1 = packdup(x.y);
#pragma unroll
        for (int i = 0; i < 4; i++) {
            acc3[0][2 * i]     = ffma2(a0, w[i].u[0], acc3[0][2 * i]);
            acc3[0][2 * i + 1] = ffma2(a0, w[i].u[1], acc3[0][2 * i + 1]);
            acc3[1][2 * i]     = ffma2(a1, w[i].u[0], acc3[1][2 * i]);
            acc3[1][2 * i + 1] = ffma2(a1, w[i].u[1], acc3[1][2 * i + 1]);
        }
    }
    {
        float* dst = (jb3 < 64) ? g_PA : g_PB;
        int col = (jb3 < 64) ? jb3 : (jb3 - 64);
#pragma unroll
        for (int q = 0; q < 2; q++) {
            float4* d4 = (float4*)&dst[(n0 + na + q) * HD + col];
#pragma unroll
            for (int i = 0; i < 4; i++) {
                U16 o;
                o.u[0] = acc3[q][2 * i]; o.u[1] = acc3[q][2 * i + 1];
                d4[i] = o.f;
            }
        }
    }
}

// ================= final =================
#define FINAL_SMEM_FLOATS (4096 * 3 + 64 * 3 + 256)
__global__ void k_final(const float* __restrict__ nmask,
                        const float* __restrict__ dw1, const float* __restrict__ db1,
                        const float* __restrict__ dw2, const float* __restrict__ db2,
                        const float* __restrict__ gw1, const float* __restrict__ gb1,
                        const float* __restrict__ gw2, const float* __restrict__ gb2,
                        const int* __restrict__ ridx, const float* __restrict__ rsign,
                        float* __restrict__ pred) {
    extern __shared__ float sm[];
    float* sD1 = sm;
    float* sD2 = sm + 4096;
    float* sG1 = sm + 8192;
    float* sDB1 = sm + 12288;
    float* sDB2 = sDB1 + 64;
    float* sGB1 = sDB2 + 64;
    float* red  = sGB1 + 64;
    int tid = threadIdx.x;
    for (int idx = tid; idx < 4096; idx += blockDim.x) {
        int k = idx >> 6, j = idx & 63;
        int si = k * 64 + ((j & 31) << 1) + (j >> 5);
        sD1[si] = dw1[k * HD + j];
        sD2[si] = dw2[k * HD + j];
        sG1[si] = gw1[k * HD + j];
    }
    if (tid < 64) { sDB1[tid] = db1[tid]; sDB2[tid] = db2[tid]; sGB1[tid] = gb1[tid]; }
    __syncthreads();
    int lane = tid & 31, wid = tid >> 5;
    int g = blockIdx.x;
    const float2* D1 = (const float2*)sD1;
    const float2* D2 = (const float2*)sD2;
    const float2* G1 = (const float2*)sG1;
    float acc0 = 0.f, acc1 = 0.f;
#pragma unroll
    for (int i = 0; i < 4; i++) {
        int n = g * NPG + wid * 4 + i;
        float hl = g_h[n * HD + lane], hh = g_h[n * HD + 32 + lane];
        float t0 = sDB1[lane], t1 = sDB1[32 + lane];
#pragma unroll
        for (int k = 0; k < 32; k++) {
            float v = __shfl_sync(0xffffffffu, hl, k);
            float2 w = D1[k * 32 + lane];
            t0 += v * w.x; t1 += v * w.y;
        }
#pragma unroll
        for (int k = 0; k < 32; k++) {
            float v = __shfl_sync(0xffffffffu, hh, k);
            float2 w = D1[(32 + k) * 32 + lane];
            t0 += v * w.x; t1 += v * w.y;
        }
        t0 = silu(t0); t1 = silu(t1);
        float o0 = sDB2[lane], o1 = sDB2[32 + lane];
#pragma unroll
        for (int k = 0; k < 32; k++) {
            float v = __shfl_sync(0xffffffffu, t0, k);
            float2 w = D2[k * 32 + lane];
            o0 += v * w.x; o1 += v * w.y;
        }
#pragma unroll
        for (int k = 0; k < 32; k++) {
            float v = __shfl_sync(0xffffffffu, t1, k);
            float2 w = D2[(32 + k) * 32 + lane];
            o0 += v * w.x; o1 += v * w.y;
        }
        float m = nmask[n];
        acc0 += o0 * m; acc1 += o1 * m;
    }
    red[wid * 64 + lane] = acc0;
    red[wid * 64 + 32 + lane] = acc1;
    __syncthreads();
    if (wid == 0) {
        float hg0 = red[lane] + red[64 + lane] + red[128 + lane] + red[192 + lane];
        float hg1 = red[32 + lane] + red[96 + lane] + red[160 + lane] + red[224 + lane];
        float t0 = sGB1[lane], t1 = sGB1[32 + lane];
#pragma unroll
        for (int k = 0; k < 32; k++) {
            float v = __shfl_sync(0xffffffffu, hg0, k);
            float2 w = G1[k * 32 + lane];
            t0 += v * w.x; t1 += v * w.y;
        }
#pragma unroll
        for (int k = 0; k < 32; k++) {
            float v = __shfl_sync(0xffffffffu, hg1, k);
            float2 w = G1[(32 + k) * 32 + lane];
            t0 += v * w.x; t1 += v * w.y;
        }
        t0 = silu(t0); t1 = silu(t1);
        float part = t0 * gw2[lane] + t1 * gw2[32 + lane];
#pragma unroll
        for (int off = 16; off > 0; off >>= 1)
            part += __shfl_xor_sync(0xffffffffu, part, off);
        if (lane == 0) {
            float val = (part + gb2[0]) * rsign[g];
            atomicAdd(&pred[ridx[g]], val);
        }
    }
}

// ================= launch =================
extern "C" void kernel_launch(void* const* d_in, const int* in_sizes, int n_in,
                              void* d_out, int out_size) {
    const float* h0    = (const float*)d_in[0];
    const float* pos   = (const float*)d_in[1];
    const int*   edges = (const int*)  d_in[2];
    const float* nmask = (const float*)d_in[3];
    const float* emask = (const float*)d_in[4];
    const int*   ridx  = (const int*)  d_in[5];
    const float* rsign = (const float*)d_in[6];
    const float* emb_w = (const float*)d_in[7];
    const float* emb_b = (const float*)d_in[8];
    const float* ew1   = (const float*)d_in[9];
    const float* eb1   = (const float*)d_in[10];
    const float* ew2   = (const float*)d_in[11];
    const float* eb2   = (const float*)d_in[12];
    const float* nw1   = (const float*)d_in[13];
    const float* nb1   = (const float*)d_in[14];
    const float* nw2   = (const float*)d_in[15];
    const float* nb2   = (const float*)d_in[16];
    const float* dw1   = (const float*)d_in[17];
    const float* db1   = (const float*)d_in[18];
    const float* dw2   = (const float*)d_in[19];
    const float* db2   = (const float*)d_in[20];
    const float* gw1   = (const float*)d_in[21];
    const float* gb1   = (const float*)d_in[22];
    const float* gw2   = (const float*)d_in[23];
    const float* gb2   = (const float*)d_in[24];
    float* pred = (float*)d_out;

    cudaFuncSetAttribute(k_su2, cudaFuncAttributeMaxDynamicSharedMemorySize,
                         P0_SMEM * 4);
    cudaFuncSetAttribute(k_edge, cudaFuncAttributeMaxDynamicSharedMemorySize,
                         EDGE_SMEM * 4);
    cudaFuncSetAttribute(k_nodefused, cudaFuncAttributeMaxDynamicSharedMemorySize,
                         NF_SMEM * 4);
    cudaFuncSetAttribute(k_final, cudaFuncAttributeMaxDynamicSharedMemorySize,
                         FINAL_SMEM_FLOATS * 4);

    // L1: embedding + zero counts
    k_su1<<<NND * HD / 256, 256>>>(h0, emb_w, emb_b);
    // L2: precomp0 (512 blocks) | radial+hist (1920 blocks)
    k_su2<<<512 + 1920, 256, P0_SMEM * 4>>>(ew1, eb1, edges, pos);
    // L3: scan (1) | zero pred (1)
    k_su3<<<2, 1024>>>(pred);
    // L4: build sorted edge arrays (used by ALL 4 layers)
    k_scatterprep<<<(NE + 255) / 256, 256>>>(edges, emask);

    for (int l = 0; l < NL; l++) {
        int last = (l == NL - 1);
        // sorted edge kernel, 2 tiles per CTA
        k_edge<<<NE / (2 * TE), 256, EDGE_SMEM * 4>>>(
            ew2 + l * HD * HD, eb2 + l * HD, ew1 + l * EINC * HD + 128 * HD);
        k_nodefused<<<NND / 64, 256, NF_SMEM * 4>>>(
            h0,
            nw1 + l * NINC * HD, nb1 + l * HD,
            nw2 + l * HD * HD, nb2 + l * HD,
            last ? (const float*)0 : (ew1 + (l + 1) * EINC * HD),
            last ? (const float*)0 : (eb1 + (l + 1) * HD),
            last);
    }

    k_final<<<NG, 128, FINAL_SMEM_FLOATS * 4>>>(
        nmask, dw1, db1, dw2, db2, gw1, gb1, gw2, gb2, ridx, rsign, pred);
}